// round 2
// baseline (speedup 1.0000x reference)
#include <cuda_runtime.h>
#include <cstdint>

#define CC  192
#define BB  8
#define HH  96
#define WW  96
#define HWH (HH*WW)     // 9216
#define CO  64
#define TH  8
#define WPS_STRIDE 66   // padded stride for transposed wp in smem (bank-friendly, 8B-aligned)

// Combined depthwise weights, broadcast-packed (w,w) per tap. Per channel 65 taps:
//   [0..48]  dense 7x7 (dy,dx in -3..3), row-major
//   [49..56] dilated-5 taps, offsets ((i-1)*5,(j-1)*5), row-major skipping center
//   [57..64] dilated-7 taps, same order with *7
__device__ float2 g_w2[CC * 65];
// ReLU'd depthwise output, [B][C][H][W]
__device__ float g_scratch[BB * CC * HH * WW];

// ---------------------------------------------------------------------------
// f32x2 helpers (bit-exact fp32 per lane; Blackwell packed-FMA pipe)
// ---------------------------------------------------------------------------
__device__ __forceinline__ uint64_t pack2(float lo, float hi) {
    uint64_t r; asm("mov.b64 %0, {%1, %2};" : "=l"(r) : "f"(lo), "f"(hi)); return r;
}
__device__ __forceinline__ void unpack2(uint64_t v, float& lo, float& hi) {
    asm("mov.b64 {%0, %1}, %2;" : "=f"(lo), "=f"(hi) : "l"(v));
}
__device__ __forceinline__ void fma2(uint64_t& d, uint64_t a, uint64_t b) {
    asm("fma.rn.f32x2 %0, %1, %2, %0;" : "+l"(d) : "l"(a), "l"(b));
}

// ---------------------------------------------------------------------------
// Prep: fold the 7 depthwise convs + a[] scaling into one 65-tap kernel/channel
// ---------------------------------------------------------------------------
__global__ void prep_kernel(const float* __restrict__ a,
                            const float* __restrict__ w1,
                            const float* __restrict__ w3,
                            const float* __restrict__ w5,
                            const float* __restrict__ w7,
                            const float* __restrict__ w35,
                            const float* __restrict__ w37) {
    int c = blockIdx.x * blockDim.x + threadIdx.x;
    if (c >= CC) return;
    float a0 = a[0], a1 = a[1], a25 = a[2] + a[5], a3 = a[3], a4 = a[4];
    float a6 = a[6], a7 = a[7];
    float d[49];
#pragma unroll
    for (int i = 0; i < 49; i++) d[i] = a4 * w7[c * 49 + i];
#pragma unroll
    for (int dy = -2; dy <= 2; dy++)
#pragma unroll
        for (int dx = -2; dx <= 2; dx++)
            d[(dy + 3) * 7 + (dx + 3)] += a3 * w5[c * 25 + (dy + 2) * 5 + (dx + 2)];
#pragma unroll
    for (int dy = -1; dy <= 1; dy++)
#pragma unroll
        for (int dx = -1; dx <= 1; dx++)
            d[(dy + 3) * 7 + (dx + 3)] += a25 * w3[c * 9 + (dy + 1) * 3 + (dx + 1)];
    // identity tap (a0*x), k1 conv, and center taps of the dilated 3x3s
    d[24] += a0 + a1 * w1[c] + a6 * w35[c * 9 + 4] + a7 * w37[c * 9 + 4];
#pragma unroll
    for (int i = 0; i < 49; i++) g_w2[c * 65 + i] = make_float2(d[i], d[i]);
    int idx = 49;
    for (int i = 0; i < 3; i++)
        for (int j = 0; j < 3; j++)
            if (i != 1 || j != 1) {
                float v = a6 * w35[c * 9 + i * 3 + j];
                g_w2[c * 65 + idx++] = make_float2(v, v);
            }
    for (int i = 0; i < 3; i++)
        for (int j = 0; j < 3; j++)
            if (i != 1 || j != 1) {
                float v = a7 * w37[c * 9 + i * 3 + j];
                g_w2[c * 65 + idx++] = make_float2(v, v);
            }
}

// ---------------------------------------------------------------------------
// Fused depthwise (65 taps) + ReLU, f32x2-packed.
// Block: (24,8) = 192 threads; tile = full width 96 x TH=8 rows of one (b,c)
// plane. Each thread computes 4 horizontal pixels as two f32x2 lane-pairs.
// Weights fetched per-use from smem as broadcast (w,w) 8B pairs.
// ---------------------------------------------------------------------------
__global__ __launch_bounds__(192) void dw_kernel(const float* __restrict__ x) {
    __shared__ __align__(16) float s[22][112];  // rows y0-7..y0+14, cols -7..102
    __shared__ __align__(8)  float2 ws2[65];

    const int c = blockIdx.y, b = blockIdx.z;
    const int y0 = blockIdx.x * TH;
    const int tid = threadIdx.y * 24 + threadIdx.x;

    for (int k = tid; k < 65; k += 192) ws2[k] = g_w2[c * 65 + k];

    const float* __restrict__ xp = x + (size_t)(b * CC + c) * HWH;
    for (int i = tid; i < 22 * 110; i += 192) {
        int sy = i / 110, sx = i - sy * 110;
        int gy = y0 + sy - 7, gx = sx - 7;
        float v = 0.f;
        if (gy >= 0 && gy < HH && (unsigned)gx < (unsigned)WW) v = xp[gy * WW + gx];
        s[sy][sx] = v;
    }
    __syncthreads();

    const int tx = threadIdx.x, ty = threadIdx.y;
    const int ox = tx * 4;

    uint64_t accA = 0ull, accB = 0ull;   // (p0,p1), (p2,p3)
    const uint64_t* wq = (const uint64_t*)ws2;

    // dense 7x7: smem row = ty+4+ky ; base col = ox+4
#pragma unroll
    for (int ky = 0; ky < 7; ky++) {
        const float* rowp = &s[ty + 4 + ky][ox + 4];
        float4 ra = *(const float4*)rowp;
        float4 rb = *(const float4*)(rowp + 4);
        float2 rc = *(const float2*)(rowp + 8);
        float r[10] = {ra.x, ra.y, ra.z, ra.w, rb.x, rb.y, rb.z, rb.w, rc.x, rc.y};
        // overlapping pairs: pe[i]=(r[2i],r[2i+1]), po[i]=(r[2i+1],r[2i+2])
        uint64_t pe[5], po[4];
#pragma unroll
        for (int i = 0; i < 5; i++) pe[i] = pack2(r[2 * i], r[2 * i + 1]);
#pragma unroll
        for (int i = 0; i < 4; i++) po[i] = pack2(r[2 * i + 1], r[2 * i + 2]);
#pragma unroll
        for (int kx = 0; kx < 7; kx++) {
            uint64_t w2 = wq[ky * 7 + kx];
            uint64_t i0 = (kx & 1) ? po[(kx - 1) >> 1] : pe[kx >> 1];        // (r[kx],r[kx+1])
            uint64_t i1 = (kx & 1) ? po[(kx + 1) >> 1] : pe[(kx >> 1) + 1]; // (r[kx+2],r[kx+3])
            fma2(accA, w2, i0);
            fma2(accB, w2, i1);
        }
    }

    // sparse taps: input col base = ox+7+dx (8B-aligned iff 7+dx even, i.e. dx odd)
#define TAP_EVEN(widx, dy, dx)                                                  \
    { uint64_t w2 = wq[widx];                                                   \
      const float* p = &s[ty + 7 + (dy)][ox + 7 + (dx)];                        \
      fma2(accA, w2, *(const uint64_t*)p);                                      \
      fma2(accB, w2, *(const uint64_t*)(p + 2)); }
#define TAP_ODD(widx, dy, dx)                                                   \
    { uint64_t w2 = wq[widx];                                                   \
      const float* p = &s[ty + 7 + (dy)][ox + 7 + (dx)];                        \
      fma2(accA, w2, pack2(p[0], p[1]));                                        \
      fma2(accB, w2, pack2(p[2], p[3])); }

    TAP_EVEN(49, -5, -5) TAP_ODD(50, -5, 0) TAP_EVEN(51, -5, 5)
    TAP_EVEN(52,  0, -5)                    TAP_EVEN(53,  0, 5)
    TAP_EVEN(54,  5, -5) TAP_ODD(55,  5, 0) TAP_EVEN(56,  5, 5)

    TAP_EVEN(57, -7, -7) TAP_ODD(58, -7, 0) TAP_EVEN(59, -7, 7)
    TAP_EVEN(60,  0, -7)                    TAP_EVEN(61,  0, 7)
    TAP_EVEN(62,  7, -7) TAP_ODD(63,  7, 0) TAP_EVEN(64,  7, 7)
#undef TAP_EVEN
#undef TAP_ODD

    float a0, a1, a2, a3;
    unpack2(accA, a0, a1);
    unpack2(accB, a2, a3);
    float4 o4 = make_float4(fmaxf(a0, 0.f), fmaxf(a1, 0.f),
                            fmaxf(a2, 0.f), fmaxf(a3, 0.f));
    *(float4*)&g_scratch[(size_t)(b * CC + c) * HWH + (y0 + ty) * WW + ox] = o4;
}

// ---------------------------------------------------------------------------
// Pointwise 1x1: out[b,o,p] = sum_c wp[o,c] * relu[b,c,p]
// GEMM tile 64 outs x 64 pixels, K=192. 128 threads = (16 px-quads, 8 o-groups).
// Per thread: 8 outs x 4 px, accumulators packed as f32x2 (o,o+1) pairs.
// ---------------------------------------------------------------------------
extern __shared__ float pw_smem[];

__global__ __launch_bounds__(128) void pw_kernel(const float* __restrict__ wp,
                                                 float* __restrict__ out) {
    float* wps = pw_smem;                      // transposed wp: [c][66] (o fast)
    float* ss  = pw_smem + CC * WPS_STRIDE;    // [16][64] scratch chunk

    const int tid = threadIdx.x;
    const int b = blockIdx.y;
    const int px0 = blockIdx.x * 64;

    // load + transpose wp (wp is [o][c], c fast -> coalesced reads)
    for (int i = tid; i < CO * CC; i += 128) {
        int o = i / CC, cc = i - o * CC;
        wps[cc * WPS_STRIDE + o] = wp[i];
    }

    const int tx = tid & 15, og = tid >> 4;
    const float* sb = g_scratch + (size_t)b * CC * HWH + px0;

    uint64_t acc[4][4];
#pragma unroll
    for (int i = 0; i < 4; i++)
#pragma unroll
        for (int j = 0; j < 4; j++) acc[i][j] = 0ull;

    for (int c0 = 0; c0 < CC; c0 += 16) {
        __syncthreads();   // first iter: wps ready; later: prev readers done
#pragma unroll
        for (int i = 0; i < 8; i++) {
            int ii = tid + i * 128;            // 16*64 = 1024 = 8*128
            int kc = ii >> 6, p = ii & 63;
            ss[kc * 64 + p] = sb[(size_t)(c0 + kc) * HWH + p];
        }
        __syncthreads();
#pragma unroll
        for (int kc = 0; kc < 16; kc++) {
            float4 sv = *(const float4*)&ss[kc * 64 + tx * 4];
            uint64_t s0 = pack2(sv.x, sv.x), s1 = pack2(sv.y, sv.y);
            uint64_t s2 = pack2(sv.z, sv.z), s3 = pack2(sv.w, sv.w);
            const float* wrow = &wps[(c0 + kc) * WPS_STRIDE + og * 8];
#pragma unroll
            for (int op = 0; op < 4; op++) {
                uint64_t w2 = *(const uint64_t*)(wrow + op * 2);  // (w[o], w[o+1])
                fma2(acc[op][0], w2, s0);
                fma2(acc[op][1], w2, s1);
                fma2(acc[op][2], w2, s2);
                fma2(acc[op][3], w2, s3);
            }
        }
    }

    float* ob = out + (size_t)b * CO * HWH + px0 + tx * 4;
#pragma unroll
    for (int op = 0; op < 4; op++) {
        float lo0, hi0, lo1, hi1, lo2, hi2, lo3, hi3;
        unpack2(acc[op][0], lo0, hi0);
        unpack2(acc[op][1], lo1, hi1);
        unpack2(acc[op][2], lo2, hi2);
        unpack2(acc[op][3], lo3, hi3);
        int o = og * 8 + op * 2;
        *(float4*)&ob[(size_t)o * HWH]       = make_float4(lo0, lo1, lo2, lo3);
        *(float4*)&ob[(size_t)(o + 1) * HWH] = make_float4(hi0, hi1, hi2, hi3);
    }
}

// ---------------------------------------------------------------------------
extern "C" void kernel_launch(void* const* d_in, const int* in_sizes, int n_in,
                              void* d_out, int out_size) {
    const float* x   = (const float*)d_in[0];
    const float* a   = (const float*)d_in[1];
    const float* w1  = (const float*)d_in[2];
    const float* w3  = (const float*)d_in[3];
    const float* w5  = (const float*)d_in[4];
    const float* w7  = (const float*)d_in[5];
    const float* w35 = (const float*)d_in[6];
    const float* w37 = (const float*)d_in[7];
    const float* wp  = (const float*)d_in[8];
    float* out = (float*)d_out;

    const int pw_smem_bytes = (CC * WPS_STRIDE + 16 * 64) * (int)sizeof(float); // 54784
    cudaFuncSetAttribute(pw_kernel, cudaFuncAttributeMaxDynamicSharedMemorySize,
                         pw_smem_bytes);

    prep_kernel<<<1, 192>>>(a, w1, w3, w5, w7, w35, w37);
    dw_kernel<<<dim3(HH / TH, CC, BB), dim3(24, 8)>>>(x);
    pw_kernel<<<dim3(HWH / 64, BB), 128, pw_smem_bytes>>>(wp, out);
}